// round 14
// baseline (speedup 1.0000x reference)
#include <cuda_runtime.h>
#include <cuda_fp16.h>
#include <math.h>
#include <stdint.h>

// ---------------- problem constants ----------------
#define NN   8192
#define EE   65536
#define GG   64
#define DNODE 64
#define DEDGE 32
#define CC   256
#define H1C  8
#define H2C  4
#define ET   (EE + NN)          // 73728 = 576*128
#define HC1  (H1C * CC)         // 2048
#define HC2  (H2C * CC)         // 1024
#define NEG_SLOPE 0.2f

// ---------------- device scratch ----------------
__device__ int    g_is64;
__device__ int    g_src[EE];
__device__ int    g_dst[EE];
__device__ int    g_batch[NN];
__device__ int    g_deg[NN];
__device__ int    g_cur[NN];
__device__ int    g_off[NN + 1];
__device__ int    g_gstart[GG];
__device__ int    g_gend[GG];
__device__ int    g_pedge[ET];
__device__ int    g_psrc[ET];
__device__ int    g_pdst[ET];
__device__ __half g_ea2h[ET * DEDGE];
__device__ __half g_xh[NN * DNODE];
__device__ __half g_xl[NN * HC1];
__device__ __half g_xr[NN * HC1];
__device__ __half g_h1h[NN * HC1];
__device__ float  g_logits[ET * H1C * 4];
__device__ float  g_pool[GG * HC2];
__device__ float  g_m1[GG * 512];
__device__ float  g_m2[GG * 256];
__device__ __half g_w1h[2 * HC1 * DNODE];
__device__ __half g_w2h[2 * HC2 * HC1];
__device__ __half g_we1h[HC1 * DEDGE];
__device__ __half g_we2h[HC2 * DEDGE];

// ---------------- helpers ----------------
__device__ __forceinline__ float warp_sum(float v) {
    #pragma unroll
    for (int o = 16; o; o >>= 1) v += __shfl_xor_sync(0xffffffffu, v, o);
    return v;
}
__device__ __forceinline__ float warp_max(float v) {
    #pragma unroll
    for (int o = 16; o; o >>= 1) v = fmaxf(v, __shfl_xor_sync(0xffffffffu, v, o));
    return v;
}
__device__ __forceinline__ uint32_t smem_u32(const void* p) {
    uint32_t a;
    asm("{ .reg .u64 t; cvta.to.shared.u64 t, %1; cvt.u32.u64 %0, t; }" : "=r"(a) : "l"(p));
    return a;
}
__device__ __forceinline__ void mma_f16(float* c, uint4 a, uint2 b) {
    asm volatile(
        "mma.sync.aligned.m16n8k16.row.col.f32.f16.f16.f32 "
        "{%0,%1,%2,%3},{%4,%5,%6,%7},{%8,%9},{%0,%1,%2,%3};"
        : "+f"(c[0]), "+f"(c[1]), "+f"(c[2]), "+f"(c[3])
        : "r"(a.x), "r"(a.y), "r"(a.z), "r"(a.w), "r"(b.x), "r"(b.y));
}
__device__ __forceinline__ uint4 ldsm4(uint32_t addr) {
    uint4 r;
    asm volatile("ldmatrix.sync.aligned.m8n8.x4.shared.b16 {%0,%1,%2,%3}, [%4];"
        : "=r"(r.x), "=r"(r.y), "=r"(r.z), "=r"(r.w) : "r"(addr));
    return r;
}
__device__ __forceinline__ void cp16(uint32_t dst, const void* src) {
    asm volatile("cp.async.cg.shared.global [%0], [%1], 16;" :: "r"(dst), "l"(src));
}

// =================================================================
// cp.async + ldmatrix fp16 GEMM (3-stage, XOR swizzle) — proven R7-13.
// =================================================================
#define GEMM_STAGE_BYTES 32768
#define GEMM_SMEM_BYTES  (3 * GEMM_STAGE_BYTES)

__device__ __forceinline__ void issue_stage(
    const __half* __restrict__ A, const __half* __restrict__ B, int K,
    int rowBase, int colBase, int k0, uint32_t abase, int tid)
{
    #pragma unroll
    for (int i = 0; i < 4; i++) {
        int id = i * 256 + tid;
        int r = id >> 3, c = id & 7;
        uint32_t off = (uint32_t)(r * 128 + ((c ^ (r & 7)) << 4));
        cp16(abase + off,         A + (size_t)(rowBase + r) * K + k0 + c * 8);
        cp16(abase + 16384 + off, B + (size_t)(colBase + r) * K + k0 + c * 8);
    }
    asm volatile("cp.async.commit_group;" ::: "memory");
}

__global__ __launch_bounds__(256, 2) void k_mma_dual(
    const __half* __restrict__ A, const __half* __restrict__ B,
    const float* __restrict__ biasL, const float* __restrict__ biasR,
    __half* __restrict__ outL, __half* __restrict__ outR,
    int M, int N, int K)
{
    extern __shared__ char smem[];
    uint32_t sb = smem_u32(smem);
    int tid = threadIdx.x;
    int wid = tid >> 5, lane = tid & 31;
    int mw = wid & 3, nw = wid >> 2;
    int gid = lane >> 2, tig = lane & 3;
    int rowBase = blockIdx.y * 128, colBase = blockIdx.x * 128;

    float acc[2][8][4];
    #pragma unroll
    for (int mt = 0; mt < 2; mt++)
        #pragma unroll
        for (int nt = 0; nt < 8; nt++)
            #pragma unroll
            for (int q = 0; q < 4; q++) acc[mt][nt][q] = 0.f;

    const int NCH = K >> 6;
    issue_stage(A, B, K, rowBase, colBase, 0, sb, tid);
    if (NCH > 1) issue_stage(A, B, K, rowBase, colBase, 64, sb + GEMM_STAGE_BYTES, tid);

    int arow = mw * 32 + (lane & 15);
    int achoff = lane >> 4;
    int brow = nw * 64 + ((lane >> 4) << 3) + (lane & 7);
    int bchoff = (lane >> 3) & 1;

    for (int c = 0; c < NCH; c++) {
        if (c + 2 <= NCH) asm volatile("cp.async.wait_group 1;" ::: "memory");
        else              asm volatile("cp.async.wait_group 0;" ::: "memory");
        __syncthreads();
        if (c + 2 < NCH)
            issue_stage(A, B, K, rowBase, colBase, (c + 2) << 6,
                        sb + ((c + 2) % 3) * GEMM_STAGE_BYTES, tid);

        uint32_t Ab = sb + (c % 3) * GEMM_STAGE_BYTES;
        uint32_t Bb = Ab + 16384;
        #pragma unroll
        for (int kstep = 0; kstep < 4; kstep++) {
            uint4 afr[2];
            #pragma unroll
            for (int mt = 0; mt < 2; mt++) {
                int row = arow + mt * 16;
                int ch = kstep * 2 + achoff;
                afr[mt] = ldsm4(Ab + row * 128 + ((ch ^ (row & 7)) << 4));
            }
            uint2 bfr[8];
            #pragma unroll
            for (int ntp = 0; ntp < 4; ntp++) {
                int row = brow + ntp * 16;
                int ch = kstep * 2 + bchoff;
                uint4 t = ldsm4(Bb + row * 128 + ((ch ^ (row & 7)) << 4));
                bfr[2 * ntp]     = make_uint2(t.x, t.y);
                bfr[2 * ntp + 1] = make_uint2(t.z, t.w);
            }
            #pragma unroll
            for (int mt = 0; mt < 2; mt++)
                #pragma unroll
                for (int nt = 0; nt < 8; nt++)
                    mma_f16(acc[mt][nt], afr[mt], bfr[nt]);
        }
    }

    int halfN = N >> 1;
    bool isR = (colBase >= halfN);
    const float* bias = isR ? biasR : biasL;
    __half* outp = isR ? outR : outL;
    int cb = colBase - (isR ? halfN : 0);

    #pragma unroll
    for (int mt = 0; mt < 2; mt++) {
        int row0 = rowBase + mw * 32 + mt * 16 + gid;
        #pragma unroll
        for (int nt = 0; nt < 8; nt++) {
            int col = cb + nw * 64 + nt * 8 + tig * 2;
            float b0 = bias[col], b1 = bias[col + 1];
            float c0 = acc[mt][nt][0] + b0, c1 = acc[mt][nt][1] + b1;
            float c2 = acc[mt][nt][2] + b0, c3 = acc[mt][nt][3] + b1;
            *reinterpret_cast<__half2*>(outp + (size_t)row0 * halfN + col)       = __floats2half2_rn(c0, c1);
            *reinterpret_cast<__half2*>(outp + (size_t)(row0 + 8) * halfN + col) = __floats2half2_rn(c2, c3);
        }
    }
}

// =================================================================
// Fused edge-feature GEMM + logits, smem-staged xl/xr gathers (R11).
// =================================================================
#define EEL_XL_OFF 16384
#define EEL_XR_OFF (16384 + 128 * 272)
#define EEL_SMEM_BYTES (16384 + 2 * 128 * 272)

__device__ __forceinline__ void ldg_tile_h(
    const __half* __restrict__ A, const __half* __restrict__ B, int K,
    int rowBase, int colBase, int kc, int tid, uint2* pa, uint2* pb)
{
    #pragma unroll
    for (int i = 0; i < 4; i++) {
        int id = i * 256 + tid;
        int r = id >> 3, c4 = id & 7;
        pa[i] = *reinterpret_cast<const uint2*>(A + (size_t)(rowBase + r) * K + kc + c4 * 4);
        pb[i] = *reinterpret_cast<const uint2*>(B + (size_t)(colBase + r) * K + kc + c4 * 4);
    }
}
__device__ __forceinline__ void sts_tile(
    uint32_t* __restrict__ sA, uint32_t* __restrict__ sB,
    int tid, const uint2* pa, const uint2* pb)
{
    #pragma unroll
    for (int i = 0; i < 4; i++) {
        int id = i * 256 + tid;
        int r = id >> 3, c4 = id & 7;
        int kstep = c4 >> 2;
        int pl = (c4 & 3) * 2;
        int mtile = r >> 4, ri = r & 15;
        int regA = ((pl & 4) ? 2 : 0) + (ri >> 3);
        int laneA = (ri & 7) * 4 + (pl & 3);
        int baseA = (kstep * 8 + mtile) * 128;
        sA[baseA + laneA * 4 + regA]       = pa[i].x;
        sA[baseA + (laneA + 1) * 4 + regA] = pa[i].y;
        int ntile = r >> 3, ni = r & 7;
        int regB = (pl & 4) ? 1 : 0;
        int laneB = ni * 4 + (pl & 3);
        int baseB = (kstep * 16 + ntile) * 64;
        sB[baseB + laneB * 2 + regB]       = pb[i].x;
        sB[baseB + (laneB + 1) * 2 + regB] = pb[i].y;
    }
}

template <int H>
__global__ __launch_bounds__(256) void k_ee_logits(
    const __half* __restrict__ A, const __half* __restrict__ B,
    const float* __restrict__ att)
{
    extern __shared__ uint32_t sm[];
    uint32_t sb = smem_u32(sm);
    int tid = threadIdx.x;
    int wid = tid >> 5, lane = tid & 31;
    int mw = wid & 3, nw = wid >> 2;
    int gid = lane >> 2, tig = lane & 3;
    int rowBase = blockIdx.y * 128, colBase = blockIdx.x * 128;
    const int HC = H * CC;

    #pragma unroll
    for (int i = 0; i < 8; i++) {
        int idx = i * 256 + tid;
        int el = idx >> 4, p = idx & 15;
        int eg = rowBase + el;
        int s = g_psrc[eg], d = g_pdst[eg];
        cp16(sb + EEL_XL_OFF + el * 272 + p * 16, g_xl + (size_t)s * HC + colBase + p * 8);
        cp16(sb + EEL_XR_OFF + el * 272 + p * 16, g_xr + (size_t)d * HC + colBase + p * 8);
    }
    asm volatile("cp.async.commit_group;" ::: "memory");

    float acc[2][8][4];
    #pragma unroll
    for (int mt = 0; mt < 2; mt++)
        #pragma unroll
        for (int nt = 0; nt < 8; nt++)
            #pragma unroll
            for (int q = 0; q < 4; q++) acc[mt][nt][q] = 0.f;

    uint2 pa[4], pb[4];
    ldg_tile_h(A, B, DEDGE, rowBase, colBase, 0, tid, pa, pb);
    sts_tile(sm, sm + 2048, tid, pa, pb);
    __syncthreads();

    #pragma unroll
    for (int kstep = 0; kstep < 2; kstep++) {
        uint4 afr[2];
        #pragma unroll
        for (int mt = 0; mt < 2; mt++)
            afr[mt] = *reinterpret_cast<const uint4*>(
                sm + (kstep * 8 + mw * 2 + mt) * 128 + lane * 4);
        uint2 bfr[8];
        #pragma unroll
        for (int nt = 0; nt < 8; nt++)
            bfr[nt] = *reinterpret_cast<const uint2*>(
                sm + 2048 + (kstep * 16 + nw * 8 + nt) * 64 + lane * 2);
        #pragma unroll
        for (int mt = 0; mt < 2; mt++)
            #pragma unroll
            for (int nt = 0; nt < 8; nt++)
                mma_f16(acc[mt][nt], afr[mt], bfr[nt]);
    }

    asm volatile("cp.async.wait_group 0;" ::: "memory");
    __syncthreads();

    int h = colBase >> 8;
    int q = ((blockIdx.x & 1) << 1) | nw;
    const __half2* sXL = reinterpret_cast<const __half2*>((const char*)sm + EEL_XL_OFF);
    const __half2* sXR = reinterpret_cast<const __half2*>((const char*)sm + EEL_XR_OFF);

    #pragma unroll
    for (int mt = 0; mt < 2; mt++) {
        int el0 = mw * 32 + mt * 16 + gid;
        int el1 = el0 + 8;
        float p0 = 0.f, p1 = 0.f;
        #pragma unroll
        for (int nt = 0; nt < 8; nt++) {
            int coff = nw * 32 + nt * 4 + tig;
            int col = colBase + nw * 64 + nt * 8 + tig * 2;
            float2 at = *reinterpret_cast<const float2*>(att + h * CC + (col & (CC - 1)));
            float2 a0 = __half22float2(sXL[el0 * 68 + coff]);
            float2 b0 = __half22float2(sXR[el0 * 68 + coff]);
            float2 a1 = __half22float2(sXL[el1 * 68 + coff]);
            float2 b1 = __half22float2(sXR[el1 * 68 + coff]);
            float v0 = acc[mt][nt][0] + a0.x + b0.x;
            float v1 = acc[mt][nt][1] + a0.y + b0.y;
            float v2 = acc[mt][nt][2] + a1.x + b1.x;
            float v3 = acc[mt][nt][3] + a1.y + b1.y;
            v0 = (v0 > 0.f) ? v0 : NEG_SLOPE * v0;
            v1 = (v1 > 0.f) ? v1 : NEG_SLOPE * v1;
            v2 = (v2 > 0.f) ? v2 : NEG_SLOPE * v2;
            v3 = (v3 > 0.f) ? v3 : NEG_SLOPE * v3;
            p0 += v0 * at.x + v1 * at.y;
            p1 += v2 * at.x + v3 * at.y;
        }
        p0 += __shfl_xor_sync(0xffffffffu, p0, 1);
        p0 += __shfl_xor_sync(0xffffffffu, p0, 2);
        p1 += __shfl_xor_sync(0xffffffffu, p1, 1);
        p1 += __shfl_xor_sync(0xffffffffu, p1, 2);
        if (tig == 0) {
            g_logits[((rowBase + el0) * H + h) * 4 + q] = p0;
            g_logits[((rowBase + el1) * H + h) * 4 + q] = p1;
        }
    }
}

// ---------------- weight / input conversion ----------------
__global__ void k_wconv(const float* __restrict__ Wl1, const float* __restrict__ Wr1,
                        const float* __restrict__ Wl2, const float* __restrict__ Wr2,
                        const float* __restrict__ We1, const float* __restrict__ We2,
                        const float* __restrict__ x)
{
    int t = blockIdx.x * blockDim.x + threadIdx.x;
    const int s1 = HC1 * DNODE;
    const int s2 = HC2 * HC1;
    const int s3 = HC1 * DEDGE;
    const int s4 = HC2 * DEDGE;
    if (t < s1) { g_w1h[t] = __float2half_rn(Wl1[t]); g_w1h[s1 + t] = __float2half_rn(Wr1[t]); }
    if (t < s2) { g_w2h[t] = __float2half_rn(Wl2[t]); g_w2h[s2 + t] = __float2half_rn(Wr2[t]); }
    if (t < s3) g_we1h[t] = __float2half_rn(We1[t]);
    if (t < s4) g_we2h[t] = __float2half_rn(We2[t]);
    if (t < NN * DNODE) g_xh[t] = __float2half_rn(x[t]);
}

// ---------------- graph prep ----------------
__global__ void k_detect(const int* __restrict__ ei) {
    int is64 = 1;
    for (int i = 0; i < 16; i++)
        if (ei[2 * i + 1] != 0) is64 = 0;
    g_is64 = is64;
}
__global__ void k_prep(const int* __restrict__ ei, const int* __restrict__ batch) {
    int t = blockIdx.x * blockDim.x + threadIdx.x;
    int is64 = g_is64;
    if (t < EE) {
        g_src[t] = is64 ? ei[2 * t]        : ei[t];
        g_dst[t] = is64 ? ei[2 * (EE + t)] : ei[EE + t];
    }
    if (t < NN) {
        g_batch[t] = is64 ? batch[2 * t] : batch[t];
        g_deg[t] = 0;
        g_cur[t] = 0;
    }
    if (t < GG) { g_gstart[t] = 0; g_gend[t] = 0; }
    if (t < GG * HC2) g_pool[t] = 0.f;
}
__global__ void k_deg() {
    int e = blockIdx.x * blockDim.x + threadIdx.x;
    if (e < EE) atomicAdd(&g_deg[g_dst[e]], 1);
}
__global__ void k_scan() {
    __shared__ int wsum[8];
    int t = threadIdx.x, lane = t & 31, wid = t >> 5;
    int base = t * 32;
    int loc[32];
    int s = 0;
    #pragma unroll
    for (int i = 0; i < 32; i++) { loc[i] = s; s += g_deg[base + i] + 1; }
    int v = s;
    #pragma unroll
    for (int o = 1; o < 32; o <<= 1) {
        int u = __shfl_up_sync(0xffffffffu, v, o);
        if (lane >= o) v += u;
    }
    if (lane == 31) wsum[wid] = v;
    __syncthreads();
    if (wid == 0) {
        int w = (lane < 8) ? wsum[lane] : 0;
        #pragma unroll
        for (int o = 1; o < 8; o <<= 1) {
            int u = __shfl_up_sync(0xffffffffu, w, o);
            if (lane >= o) w += u;
        }
        if (lane < 8) wsum[lane] = w;
    }
    __syncthreads();
    int p = v - s + (wid > 0 ? wsum[wid - 1] : 0);
    #pragma unroll
    for (int i = 0; i < 32; i++) g_off[base + i] = p + loc[i];
    if (t == 255) g_off[NN] = p + s;
}
__global__ void k_csr() {
    int e = blockIdx.x * blockDim.x + threadIdx.x;
    if (e >= ET) return;
    int s, node;
    if (e < EE) { s = g_src[e]; node = g_dst[e]; } else { s = node = e - EE; }
    int pos = g_off[node] + atomicAdd(&g_cur[node], 1);
    g_pedge[pos] = e;
    g_psrc[pos]  = s;
    g_pdst[pos]  = node;
    if (e < NN) {
        int b = g_batch[e];
        if (e == 0 || g_batch[e - 1] != b) g_gstart[b] = e;
        if (e == NN - 1 || g_batch[e + 1] != b) g_gend[b] = e + 1;
    }
}
__global__ void k_ea2(const float* __restrict__ ea) {
    int t = blockIdx.x * blockDim.x + threadIdx.x;
    if (t >= ET * DEDGE) return;
    int pos = t >> 5, d = t & 31;
    int e = g_pedge[pos];
    float v;
    if (e < EE) {
        v = ea[e * DEDGE + d];
    } else {
        int n = e - EE;
        int s0 = g_off[n], s1 = g_off[n + 1];
        float sum = 0.f;
        for (int p = s0; p < s1; p++) {
            int ee = g_pedge[p];
            if (ee < EE) sum += ea[ee * DEDGE + d];
        }
        v = sum / fmaxf((float)(s1 - s0 - 1), 1.f);
    }
    g_ea2h[t] = __float2half_rn(v);
}

// ---------------- fp32 SGEMM for the tiny MLP ----------------
__global__ __launch_bounds__(256) void k_sgemm(
    const float* __restrict__ A, const float* __restrict__ Bm,
    const float* __restrict__ bias, float* __restrict__ Cm,
    int M, int Nc, int K, int act)
{
    constexpr int BM = 128, BN = 128, BK = 16, TM = 8, TN = 8;
    __shared__ float As[BK][BM];
    __shared__ float Bs[BK][BN];
    int tid = threadIdx.x;
    int tx = tid % 16, ty = tid / 16;
    int rowBase = blockIdx.y * BM;
    int colBase = blockIdx.x * BN;
    float acc[TM][TN];
    #pragma unroll
    for (int i = 0; i < TM; i++)
        #pragma unroll
        for (int j = 0; j < TN; j++) acc[i][j] = 0.f;
    for (int k0 = 0; k0 < K; k0 += BK) {
        #pragma unroll
        for (int i = 0; i < 2; i++) {
            int f4 = tid + i * 256;
            int r = f4 >> 2;
            int kk = (f4 & 3) * 4;
            int gr = rowBase + r;
            float4 v = make_float4(0.f, 0.f, 0.f, 0.f);
            if (gr < M) v = *reinterpret_cast<const float4*>(A + (size_t)gr * K + k0 + kk);
            As[kk + 0][r] = v.x; As[kk + 1][r] = v.y; As[kk + 2][r] = v.z; As[kk + 3][r] = v.w;
            int gc = colBase + r;
            float4 w = make_float4(0.f, 0.f, 0.f, 0.f);
            if (gc < Nc) w = *reinterpret_cast<const float4*>(Bm + (size_t)gc * K + k0 + kk);
            Bs[kk + 0][r] = w.x; Bs[kk + 1][r] = w.y; Bs[kk + 2][r] = w.z; Bs[kk + 3][r] = w.w;
        }
        __syncthreads();
        #pragma unroll
        for (int k = 0; k < BK; k++) {
            float a[TM], b[TN];
            #pragma unroll
            for (int i = 0; i < TM; i++) a[i] = As[k][ty * TM + i];
            #pragma unroll
            for (int j = 0; j < TN; j++) b[j] = Bs[k][tx * TN + j];
            #pragma unroll
            for (int i = 0; i < TM; i++)
                #pragma unroll
                for (int j = 0; j < TN; j++) acc[i][j] = fmaf(a[i], b[j], acc[i][j]);
        }
        __syncthreads();
    }
    #pragma unroll
    for (int i = 0; i < TM; i++) {
        int gr = rowBase + ty * TM + i;
        if (gr >= M) continue;
        #pragma unroll
        for (int j = 0; j < TN; j++) {
            int gc = colBase + tx * TN + j;
            if (gc >= Nc) continue;
            float v = acc[i][j];
            if (bias) v += bias[gc];
            if (act) v = fmaxf(v, 0.f);
            Cm[(size_t)gr * Nc + gc] = v;
        }
    }
}

// ---------------- segment softmax + weighted gather (csr order) ----------------
// Lane owns 8 contiguous columns: col0 = h*CC + lane*8. One LDG.128 per edge.
template <int H, int RELU, int OUTMODE>
__global__ void k_aggregate(const float* __restrict__ bias, void* __restrict__ out) {
    int n = blockIdx.x;
    int h = threadIdx.x >> 5, lane = threadIdx.x & 31;
    int s0 = g_off[n], s1 = g_off[n + 1];
    int cnt = s1 - s0;
    const int ROW4 = H * CC / 8;     // uint4 per node row
    const uint4* xlv = reinterpret_cast<const uint4*>(g_xl);
    int rbase = h * 32 + lane;       // uint4 index within row for this lane/head
    float acc[8];
    #pragma unroll
    for (int j = 0; j < 8; j++) acc[j] = 0.f;

    if (cnt <= 64) {
        int cs0 = 0, cs1 = 0;
        float lv0 = -1e30f, lv1 = -1e30f;
        if (lane < cnt) {
            int p = s0 + lane;
            cs0 = g_psrc[p];
            float4 lg = *reinterpret_cast<const float4*>(&g_logits[(p * H + h) * 4]);
            lv0 = (lg.x + lg.y) + (lg.z + lg.w);
        }
        if (lane + 32 < cnt) {
            int p = s0 + lane + 32;
            cs1 = g_psrc[p];
            float4 lg = *reinterpret_cast<const float4*>(&g_logits[(p * H + h) * 4]);
            lv1 = (lg.x + lg.y) + (lg.z + lg.w);
        }
        float mx = warp_max(fmaxf(lv0, lv1));
        float ex0 = (lane < cnt)      ? __expf(lv0 - mx) : 0.f;
        float ex1 = (lane + 32 < cnt) ? __expf(lv1 - mx) : 0.f;
        float inv = 1.f / warp_sum(ex0 + ex1);
        for (int i = 0; i < cnt; i++) {
            int srcl = i & 31;
            float w = __shfl_sync(0xffffffffu, (i < 32) ? ex0 : ex1, srcl) * inv;
            int s = __shfl_sync(0xffffffffu, (i < 32) ? cs0 : cs1, srcl);
            uint4 f = xlv[(size_t)s * ROW4 + rbase];
            float2 f0 = __half22float2(*reinterpret_cast<__half2*>(&f.x));
            float2 f1 = __half22float2(*reinterpret_cast<__half2*>(&f.y));
            float2 f2 = __half22float2(*reinterpret_cast<__half2*>(&f.z));
            float2 f3 = __half22float2(*reinterpret_cast<__half2*>(&f.w));
            acc[0] = fmaf(w, f0.x, acc[0]); acc[1] = fmaf(w, f0.y, acc[1]);
            acc[2] = fmaf(w, f1.x, acc[2]); acc[3] = fmaf(w, f1.y, acc[3]);
            acc[4] = fmaf(w, f2.x, acc[4]); acc[5] = fmaf(w, f2.y, acc[5]);
            acc[6] = fmaf(w, f3.x, acc[6]); acc[7] = fmaf(w, f3.y, acc[7]);
        }
    } else {
        float mx = -1e30f;
        for (int i = s0 + lane; i < s1; i += 32) {
            float4 lg = *reinterpret_cast<const float4*>(&g_logits[(i * H + h) * 4]);
            mx = fmaxf(mx, (lg.x + lg.y) + (lg.z + lg.w));
        }
        mx = warp_max(mx);
        float den = 0.f;
        for (int i = s0 + lane; i < s1; i += 32) {
            float4 lg = *reinterpret_cast<const float4*>(&g_logits[(i * H + h) * 4]);
            den += __expf((lg.x + lg.y) + (lg.z + lg.w) - mx);
        }
        den = warp_sum(den);
        float inv = 1.f / den;
        for (int i = s0; i < s1; i++) {
            float4 lg = *reinterpret_cast<const float4*>(&g_logits[(i * H + h) * 4]);
            float w = __expf((lg.x + lg.y) + (lg.z + lg.w) - mx) * inv;
            int s = g_psrc[i];
            uint4 f = xlv[(size_t)s * ROW4 + rbase];
            float2 f0 = __half22float2(*reinterpret_cast<__half2*>(&f.x));
            float2 f1 = __half22float2(*reinterpret_cast<__half2*>(&f.y));
            float2 f2 = __half22float2(*reinterpret_cast<__half2*>(&f.z));
            float2 f3 = __half22float2(*reinterpret_cast<__half2*>(&f.w));
            acc[0] = fmaf(w, f0.x, acc[0]); acc[1] = fmaf(w, f0.y, acc[1]);
            acc[2] = fmaf(w, f1.x, acc[2]); acc[3] = fmaf(w, f1.y, acc[3]);
            acc[4] = fmaf(w, f2.x, acc[4]); acc[5] = fmaf(w, f2.y, acc[5]);
            acc[6] = fmaf(w, f3.x, acc[6]); acc[7] = fmaf(w, f3.y, acc[7]);
        }
    }

    int col0 = h * CC + lane * 8;
    float4 b0 = *reinterpret_cast<const float4*>(bias + col0);
    float4 b1 = *reinterpret_cast<const float4*>(bias + col0 + 4);
    float v[8];
    v[0] = acc[0] + b0.x; v[1] = acc[1] + b0.y; v[2] = acc[2] + b0.z; v[3] = acc[3] + b0.w;
    v[4] = acc[4] + b1.x; v[5] = acc[5] + b1.y; v[6] = acc[6] + b1.z; v[7] = acc[7] + b1.w;
    if (RELU) {
        #pragma unroll
        for (int j = 0; j < 8; j++) v[j] = fmaxf(v[j], 0.f);
    }
    if (OUTMODE == 1) {
        __half* oh = (__half*)out;
        uint4 pk;
        __half2 t0 = __floats2half2_rn(v[0], v[1]); pk.x = *(uint32_t*)&t0;
        __half2 t1 = __floats2half2_rn(v[2], v[3]); pk.y = *(uint32_t*)&t1;
        __half2 t2 = __floats2half2_rn(v[4], v[5]); pk.z = *(uint32_t*)&t2;
        __half2 t3 = __floats2half2_rn(v[6], v[7]); pk.w = *(uint32_t*)&t3;
        *reinterpret_cast<uint4*>(oh + (size_t)n * (H * CC) + col0) = pk;
    } else if (OUTMODE == 0) {
        float* of = (float*)out;
        *reinterpret_cast<float4*>(of + (size_t)n * (H * CC) + col0)     = make_float4(v[0], v[1], v[2], v[3]);
        *reinterpret_cast<float4*>(of + (size_t)n * (H * CC) + col0 + 4) = make_float4(v[4], v[5], v[6], v[7]);
    } else {
        int b = g_batch[n];
        #pragma unroll
        for (int j = 0; j < 8; j++) atomicAdd(&g_pool[b * HC2 + col0 + j], v[j]);
    }
}

// ---------------- pool divide + final ----------------
__global__ void k_pool_div() {
    int t = blockIdx.x * blockDim.x + threadIdx.x;
    if (t >= GG * HC2) return;
    int g = t >> 10;
    float cnt = (float)(g_gend[g] - g_gstart[g]);
    g_pool[t] /= fmaxf(cnt, 1.f);
}
__global__ void k_final(const float* __restrict__ W3, const float* __restrict__ b3,
                        float* __restrict__ out) {
    int g = blockIdx.x, lane = threadIdx.x;
    float acc = 0.f;
    #pragma unroll
    for (int j = 0; j < 8; j++) acc += g_m2[g * 256 + lane + 32 * j] * W3[lane + 32 * j];
    acc = warp_sum(acc);
    if (lane == 0) out[g] = 1.f / (1.f + expf(-(acc + b3[0])));
}

// ---------------- host launch ----------------
static inline void launch_sgemm(const float* A, const float* B, const float* bias,
                                float* C, int M, int Nc, int K, int act) {
    dim3 grid((Nc + 127) / 128, (M + 127) / 128);
    k_sgemm<<<grid, 256>>>(A, B, bias, C, M, Nc, K, act);
}

extern "C" void kernel_launch(void* const* d_in, const int* in_sizes, int n_in,
                              void* d_out, int out_size) {
    const float* x     = (const float*)d_in[0];
    const int*   ei    = (const int*)  d_in[1];
    const float* ea    = (const float*)d_in[2];
    const int*   batch = (const int*)  d_in[3];
    const float* Wl1 = (const float*)d_in[4],  *bl1 = (const float*)d_in[5];
    const float* Wr1 = (const float*)d_in[6],  *br1 = (const float*)d_in[7];
    const float* We1 = (const float*)d_in[8],  *att1 = (const float*)d_in[9];
    const float* bias1 = (const float*)d_in[10];
    const float* Wl2 = (const float*)d_in[11], *bl2 = (const float*)d_in[12];
    const float* Wr2 = (const float*)d_in[13], *br2 = (const float*)d_in[14];
    const float* We2 = (const float*)d_in[15], *att2 = (const float*)d_in[16];
    const float* bias2 = (const float*)d_in[17];
    const float* W1 = (const float*)d_in[18], *b1 = (const float*)d_in[19];
    const float* W2 = (const float*)d_in[20], *b2 = (const float*)d_in[21];
    const float* W3 = (const float*)d_in[22], *b3 = (const float*)d_in[23];
    float* out = (float*)d_out;

    static int s_init = 0;
    static cudaStream_t s1;
    static cudaEvent_t eFork, eJoin;
    if (!s_init) {
        cudaFuncSetAttribute(k_mma_dual, cudaFuncAttributeMaxDynamicSharedMemorySize, GEMM_SMEM_BYTES);
        cudaFuncSetAttribute(k_ee_logits<H1C>, cudaFuncAttributeMaxDynamicSharedMemorySize, EEL_SMEM_BYTES);
        cudaFuncSetAttribute(k_ee_logits<H2C>, cudaFuncAttributeMaxDynamicSharedMemorySize, EEL_SMEM_BYTES);
        cudaStreamCreateWithFlags(&s1, cudaStreamNonBlocking);
        cudaEventCreateWithFlags(&eFork, cudaEventDisableTiming);
        cudaEventCreateWithFlags(&eJoin, cudaEventDisableTiming);
        s_init = 1;
    }

    float *p_pool, *p_m1, *p_m2;
    __half *p_xl, *p_xr, *p_h1h, *p_ea2h, *p_w1h, *p_w2h, *p_we1h, *p_we2h, *p_xh;
    cudaGetSymbolAddress((void**)&p_xl,    g_xl);
    cudaGetSymbolAddress((void**)&p_xr,    g_xr);
    cudaGetSymbolAddress((void**)&p_h1h,   g_h1h);
    cudaGetSymbolAddress((void**)&p_ea2h,  g_ea2h);
    cudaGetSymbolAddress((void**)&p_w1h,   g_w1h);
    cudaGetSymbolAddress((void**)&p_w2h,   g_w2h);
    cudaGetSymbolAddress((void**)&p_we1h,  g_we1h);
    cudaGetSymbolAddress((void**)&p_we2h,  g_we2h);
    cudaGetSymbolAddress((void**)&p_xh,    g_xh);
    cudaGetSymbolAddress((void**)&p_pool,  g_pool);
    cudaGetSymbolAddress((void**)&p_m1,    g_m1);
    cudaGetSymbolAddress((void**)&p_m2,    g_m2);

    // --- fork: graph-prep chain on s1, GEMM path on default stream ---
    cudaEventRecord(eFork, 0);
    cudaStreamWaitEvent(s1, eFork, 0);

    k_detect<<<1, 1, 0, s1>>>(ei);
    k_prep<<<(EE + 255) / 256, 256, 0, s1>>>(ei, batch);
    k_deg<<<(EE + 255) / 256, 256, 0, s1>>>();
    k_scan<<<1, 256, 0, s1>>>();
    k_csr<<<(ET + 255) / 256, 256, 0, s1>>>();
    k_ea2<<<(ET * DEDGE + 255) / 256, 256, 0, s1>>>(ea);
    cudaEventRecord(eJoin, s1);

    k_wconv<<<(HC2 * HC1 + 255) / 256, 256>>>(Wl1, Wr1, Wl2, Wr2, We1, We2, x);
    k_mma_dual<<<dim3(2 * HC1 / 128, NN / 128), 256, GEMM_SMEM_BYTES>>>(
        p_xh, p_w1h, bl1, br1, p_xl, p_xr, NN, 2 * HC1, DNODE);

    cudaStreamWaitEvent(0, eJoin, 0);

    // --- GATv2 layer 1 ---
    k_ee_logits<H1C><<<dim3(HC1 / 128, ET / 128), 256, EEL_SMEM_BYTES>>>(p_ea2h, p_we1h, att1);
    k_aggregate<H1C, 1, 1><<<NN, H1C * 32>>>(bias1, p_h1h);

    // --- GATv2 layer 2 (aggregate pools directly) ---
    k_mma_dual<<<dim3(2 * HC2 / 128, NN / 128), 256, GEMM_SMEM_BYTES>>>(
        p_h1h, p_w2h, bl2, br2, p_xl, p_xr, NN, 2 * HC2, HC1);
    k_ee_logits<H2C><<<dim3(HC2 / 128, ET / 128), 256, EEL_SMEM_BYTES>>>(p_ea2h, p_we2h, att2);
    k_aggregate<H2C, 0, 2><<<NN, H2C * 32>>>(bias2, nullptr);

    // --- pool + MLP ---
    k_pool_div<<<(GG * HC2 + 255) / 256, 256>>>();
    launch_sgemm(p_pool, W1, b1, p_m1, GG, 512, HC2, 1);
    launch_sgemm(p_m1,  W2, b2, p_m2, GG, 256, 512, 1);
    k_final<<<GG, 32>>>(W3, b3, out);
}

// round 15
// speedup vs baseline: 1.8768x; 1.8768x over previous
#include <cuda_runtime.h>
#include <cuda_fp16.h>
#include <math.h>
#include <stdint.h>

// ---------------- problem constants ----------------
#define NN   8192
#define EE   65536
#define GG   64
#define DNODE 64
#define DEDGE 32
#define CC   256
#define H1C  8
#define H2C  4
#define ET   (EE + NN)          // 73728 = 576*128
#define HC1  (H1C * CC)         // 2048
#define HC2  (H2C * CC)         // 1024
#define NEG_SLOPE 0.2f

// ---------------- device scratch ----------------
__device__ int    g_is64;
__device__ int    g_src[EE];
__device__ int    g_dst[EE];
__device__ int    g_batch[NN];
__device__ int    g_deg[NN];
__device__ int    g_cur[NN];
__device__ int    g_off[NN + 1];
__device__ int    g_gstart[GG];
__device__ int    g_gend[GG];
__device__ int    g_pedge[ET];
__device__ int    g_psrc[ET];
__device__ int    g_pdst[ET];
__device__ __half g_ea2h[ET * DEDGE];
__device__ __half g_xh[NN * DNODE];
__device__ __half g_xl[NN * HC1];
__device__ __half g_xr[NN * HC1];
__device__ __half g_h1h[NN * HC1];
__device__ float  g_logits[ET * H1C * 4];
__device__ float  g_pool[GG * HC2];
__device__ __half g_w1h[2 * HC1 * DNODE];
__device__ __half g_w2h[2 * HC2 * HC1];
__device__ __half g_we1h[HC1 * DEDGE];
__device__ __half g_we2h[HC2 * DEDGE];

// ---------------- helpers ----------------
__device__ __forceinline__ float warp_sum(float v) {
    #pragma unroll
    for (int o = 16; o; o >>= 1) v += __shfl_xor_sync(0xffffffffu, v, o);
    return v;
}
__device__ __forceinline__ float warp_max(float v) {
    #pragma unroll
    for (int o = 16; o; o >>= 1) v = fmaxf(v, __shfl_xor_sync(0xffffffffu, v, o));
    return v;
}
__device__ __forceinline__ uint32_t smem_u32(const void* p) {
    uint32_t a;
    asm("{ .reg .u64 t; cvta.to.shared.u64 t, %1; cvt.u32.u64 %0, t; }" : "=r"(a) : "l"(p));
    return a;
}
__device__ __forceinline__ void mma_f16(float* c, uint4 a, uint2 b) {
    asm volatile(
        "mma.sync.aligned.m16n8k16.row.col.f32.f16.f16.f32 "
        "{%0,%1,%2,%3},{%4,%5,%6,%7},{%8,%9},{%0,%1,%2,%3};"
        : "+f"(c[0]), "+f"(c[1]), "+f"(c[2]), "+f"(c[3])
        : "r"(a.x), "r"(a.y), "r"(a.z), "r"(a.w), "r"(b.x), "r"(b.y));
}
__device__ __forceinline__ uint4 ldsm4(uint32_t addr) {
    uint4 r;
    asm volatile("ldmatrix.sync.aligned.m8n8.x4.shared.b16 {%0,%1,%2,%3}, [%4];"
        : "=r"(r.x), "=r"(r.y), "=r"(r.z), "=r"(r.w) : "r"(addr));
    return r;
}
__device__ __forceinline__ void cp16(uint32_t dst, const void* src) {
    asm volatile("cp.async.cg.shared.global [%0], [%1], 16;" :: "r"(dst), "l"(src));
}

// =================================================================
// cp.async + ldmatrix fp16 GEMM (3-stage, XOR swizzle) — proven R7-13.
// =================================================================
#define GEMM_STAGE_BYTES 32768
#define GEMM_SMEM_BYTES  (3 * GEMM_STAGE_BYTES)

__device__ __forceinline__ void issue_stage(
    const __half* __restrict__ A, const __half* __restrict__ B, int K,
    int rowBase, int colBase, int k0, uint32_t abase, int tid)
{
    #pragma unroll
    for (int i = 0; i < 4; i++) {
        int id = i * 256 + tid;
        int r = id >> 3, c = id & 7;
        uint32_t off = (uint32_t)(r * 128 + ((c ^ (r & 7)) << 4));
        cp16(abase + off,         A + (size_t)(rowBase + r) * K + k0 + c * 8);
        cp16(abase + 16384 + off, B + (size_t)(colBase + r) * K + k0 + c * 8);
    }
    asm volatile("cp.async.commit_group;" ::: "memory");
}

__global__ __launch_bounds__(256, 2) void k_mma_dual(
    const __half* __restrict__ A, const __half* __restrict__ B,
    const float* __restrict__ biasL, const float* __restrict__ biasR,
    __half* __restrict__ outL, __half* __restrict__ outR,
    int M, int N, int K)
{
    extern __shared__ char smem[];
    uint32_t sb = smem_u32(smem);
    int tid = threadIdx.x;
    int wid = tid >> 5, lane = tid & 31;
    int mw = wid & 3, nw = wid >> 2;
    int gid = lane >> 2, tig = lane & 3;
    int rowBase = blockIdx.y * 128, colBase = blockIdx.x * 128;

    float acc[2][8][4];
    #pragma unroll
    for (int mt = 0; mt < 2; mt++)
        #pragma unroll
        for (int nt = 0; nt < 8; nt++)
            #pragma unroll
            for (int q = 0; q < 4; q++) acc[mt][nt][q] = 0.f;

    const int NCH = K >> 6;
    issue_stage(A, B, K, rowBase, colBase, 0, sb, tid);
    if (NCH > 1) issue_stage(A, B, K, rowBase, colBase, 64, sb + GEMM_STAGE_BYTES, tid);

    int arow = mw * 32 + (lane & 15);
    int achoff = lane >> 4;
    int brow = nw * 64 + ((lane >> 4) << 3) + (lane & 7);
    int bchoff = (lane >> 3) & 1;

    for (int c = 0; c < NCH; c++) {
        if (c + 2 <= NCH) asm volatile("cp.async.wait_group 1;" ::: "memory");
        else              asm volatile("cp.async.wait_group 0;" ::: "memory");
        __syncthreads();
        if (c + 2 < NCH)
            issue_stage(A, B, K, rowBase, colBase, (c + 2) << 6,
                        sb + ((c + 2) % 3) * GEMM_STAGE_BYTES, tid);

        uint32_t Ab = sb + (c % 3) * GEMM_STAGE_BYTES;
        uint32_t Bb = Ab + 16384;
        #pragma unroll
        for (int kstep = 0; kstep < 4; kstep++) {
            uint4 afr[2];
            #pragma unroll
            for (int mt = 0; mt < 2; mt++) {
                int row = arow + mt * 16;
                int ch = kstep * 2 + achoff;
                afr[mt] = ldsm4(Ab + row * 128 + ((ch ^ (row & 7)) << 4));
            }
            uint2 bfr[8];
            #pragma unroll
            for (int ntp = 0; ntp < 4; ntp++) {
                int row = brow + ntp * 16;
                int ch = kstep * 2 + bchoff;
                uint4 t = ldsm4(Bb + row * 128 + ((ch ^ (row & 7)) << 4));
                bfr[2 * ntp]     = make_uint2(t.x, t.y);
                bfr[2 * ntp + 1] = make_uint2(t.z, t.w);
            }
            #pragma unroll
            for (int mt = 0; mt < 2; mt++)
                #pragma unroll
                for (int nt = 0; nt < 8; nt++)
                    mma_f16(acc[mt][nt], afr[mt], bfr[nt]);
        }
    }

    int halfN = N >> 1;
    bool isR = (colBase >= halfN);
    const float* bias = isR ? biasR : biasL;
    __half* outp = isR ? outR : outL;
    int cb = colBase - (isR ? halfN : 0);

    #pragma unroll
    for (int mt = 0; mt < 2; mt++) {
        int row0 = rowBase + mw * 32 + mt * 16 + gid;
        #pragma unroll
        for (int nt = 0; nt < 8; nt++) {
            int col = cb + nw * 64 + nt * 8 + tig * 2;
            float b0 = bias[col], b1 = bias[col + 1];
            float c0 = acc[mt][nt][0] + b0, c1 = acc[mt][nt][1] + b1;
            float c2 = acc[mt][nt][2] + b0, c3 = acc[mt][nt][3] + b1;
            *reinterpret_cast<__half2*>(outp + (size_t)row0 * halfN + col)       = __floats2half2_rn(c0, c1);
            *reinterpret_cast<__half2*>(outp + (size_t)(row0 + 8) * halfN + col) = __floats2half2_rn(c2, c3);
        }
    }
}

// =================================================================
// Fused edge-feature GEMM + logits, smem-staged xl/xr gathers (R11).
// =================================================================
#define EEL_XL_OFF 16384
#define EEL_XR_OFF (16384 + 128 * 272)
#define EEL_SMEM_BYTES (16384 + 2 * 128 * 272)

__device__ __forceinline__ void ldg_tile_h(
    const __half* __restrict__ A, const __half* __restrict__ B, int K,
    int rowBase, int colBase, int kc, int tid, uint2* pa, uint2* pb)
{
    #pragma unroll
    for (int i = 0; i < 4; i++) {
        int id = i * 256 + tid;
        int r = id >> 3, c4 = id & 7;
        pa[i] = *reinterpret_cast<const uint2*>(A + (size_t)(rowBase + r) * K + kc + c4 * 4);
        pb[i] = *reinterpret_cast<const uint2*>(B + (size_t)(colBase + r) * K + kc + c4 * 4);
    }
}
__device__ __forceinline__ void sts_tile(
    uint32_t* __restrict__ sA, uint32_t* __restrict__ sB,
    int tid, const uint2* pa, const uint2* pb)
{
    #pragma unroll
    for (int i = 0; i < 4; i++) {
        int id = i * 256 + tid;
        int r = id >> 3, c4 = id & 7;
        int kstep = c4 >> 2;
        int pl = (c4 & 3) * 2;
        int mtile = r >> 4, ri = r & 15;
        int regA = ((pl & 4) ? 2 : 0) + (ri >> 3);
        int laneA = (ri & 7) * 4 + (pl & 3);
        int baseA = (kstep * 8 + mtile) * 128;
        sA[baseA + laneA * 4 + regA]       = pa[i].x;
        sA[baseA + (laneA + 1) * 4 + regA] = pa[i].y;
        int ntile = r >> 3, ni = r & 7;
        int regB = (pl & 4) ? 1 : 0;
        int laneB = ni * 4 + (pl & 3);
        int baseB = (kstep * 16 + ntile) * 64;
        sB[baseB + laneB * 2 + regB]       = pb[i].x;
        sB[baseB + (laneB + 1) * 2 + regB] = pb[i].y;
    }
}

template <int H>
__global__ __launch_bounds__(256) void k_ee_logits(
    const __half* __restrict__ A, const __half* __restrict__ B,
    const float* __restrict__ att)
{
    extern __shared__ uint32_t sm[];
    uint32_t sb = smem_u32(sm);
    int tid = threadIdx.x;
    int wid = tid >> 5, lane = tid & 31;
    int mw = wid & 3, nw = wid >> 2;
    int gid = lane >> 2, tig = lane & 3;
    int rowBase = blockIdx.y * 128, colBase = blockIdx.x * 128;
    const int HC = H * CC;

    #pragma unroll
    for (int i = 0; i < 8; i++) {
        int idx = i * 256 + tid;
        int el = idx >> 4, p = idx & 15;
        int eg = rowBase + el;
        int s = g_psrc[eg], d = g_pdst[eg];
        cp16(sb + EEL_XL_OFF + el * 272 + p * 16, g_xl + (size_t)s * HC + colBase + p * 8);
        cp16(sb + EEL_XR_OFF + el * 272 + p * 16, g_xr + (size_t)d * HC + colBase + p * 8);
    }
    asm volatile("cp.async.commit_group;" ::: "memory");

    float acc[2][8][4];
    #pragma unroll
    for (int mt = 0; mt < 2; mt++)
        #pragma unroll
        for (int nt = 0; nt < 8; nt++)
            #pragma unroll
            for (int q = 0; q < 4; q++) acc[mt][nt][q] = 0.f;

    uint2 pa[4], pb[4];
    ldg_tile_h(A, B, DEDGE, rowBase, colBase, 0, tid, pa, pb);
    sts_tile(sm, sm + 2048, tid, pa, pb);
    __syncthreads();

    #pragma unroll
    for (int kstep = 0; kstep < 2; kstep++) {
        uint4 afr[2];
        #pragma unroll
        for (int mt = 0; mt < 2; mt++)
            afr[mt] = *reinterpret_cast<const uint4*>(
                sm + (kstep * 8 + mw * 2 + mt) * 128 + lane * 4);
        uint2 bfr[8];
        #pragma unroll
        for (int nt = 0; nt < 8; nt++)
            bfr[nt] = *reinterpret_cast<const uint2*>(
                sm + 2048 + (kstep * 16 + nw * 8 + nt) * 64 + lane * 2);
        #pragma unroll
        for (int mt = 0; mt < 2; mt++)
            #pragma unroll
            for (int nt = 0; nt < 8; nt++)
                mma_f16(acc[mt][nt], afr[mt], bfr[nt]);
    }

    asm volatile("cp.async.wait_group 0;" ::: "memory");
    __syncthreads();

    int h = colBase >> 8;
    int q = ((blockIdx.x & 1) << 1) | nw;
    const __half2* sXL = reinterpret_cast<const __half2*>((const char*)sm + EEL_XL_OFF);
    const __half2* sXR = reinterpret_cast<const __half2*>((const char*)sm + EEL_XR_OFF);

    #pragma unroll
    for (int mt = 0; mt < 2; mt++) {
        int el0 = mw * 32 + mt * 16 + gid;
        int el1 = el0 + 8;
        float p0 = 0.f, p1 = 0.f;
        #pragma unroll
        for (int nt = 0; nt < 8; nt++) {
            int coff = nw * 32 + nt * 4 + tig;
            int col = colBase + nw * 64 + nt * 8 + tig * 2;
            float2 at = *reinterpret_cast<const float2*>(att + h * CC + (col & (CC - 1)));
            float2 a0 = __half22float2(sXL[el0 * 68 + coff]);
            float2 b0 = __half22float2(sXR[el0 * 68 + coff]);
            float2 a1 = __half22float2(sXL[el1 * 68 + coff]);
            float2 b1 = __half22float2(sXR[el1 * 68 + coff]);
            float v0 = acc[mt][nt][0] + a0.x + b0.x;
            float v1 = acc[mt][nt][1] + a0.y + b0.y;
            float v2 = acc[mt][nt][2] + a1.x + b1.x;
            float v3 = acc[mt][nt][3] + a1.y + b1.y;
            v0 = (v0 > 0.f) ? v0 : NEG_SLOPE * v0;
            v1 = (v1 > 0.f) ? v1 : NEG_SLOPE * v1;
            v2 = (v2 > 0.f) ? v2 : NEG_SLOPE * v2;
            v3 = (v3 > 0.f) ? v3 : NEG_SLOPE * v3;
            p0 += v0 * at.x + v1 * at.y;
            p1 += v2 * at.x + v3 * at.y;
        }
        p0 += __shfl_xor_sync(0xffffffffu, p0, 1);
        p0 += __shfl_xor_sync(0xffffffffu, p0, 2);
        p1 += __shfl_xor_sync(0xffffffffu, p1, 1);
        p1 += __shfl_xor_sync(0xffffffffu, p1, 2);
        if (tig == 0) {
            g_logits[((rowBase + el0) * H + h) * 4 + q] = p0;
            g_logits[((rowBase + el1) * H + h) * 4 + q] = p1;
        }
    }
}

// ---------------- weight / input conversion ----------------
__global__ void k_wconv(const float* __restrict__ Wl1, const float* __restrict__ Wr1,
                        const float* __restrict__ Wl2, const float* __restrict__ Wr2,
                        const float* __restrict__ We1, const float* __restrict__ We2,
                        const float* __restrict__ x)
{
    int t = blockIdx.x * blockDim.x + threadIdx.x;
    const int s1 = HC1 * DNODE;
    const int s2 = HC2 * HC1;
    const int s3 = HC1 * DEDGE;
    const int s4 = HC2 * DEDGE;
    if (t < s1) { g_w1h[t] = __float2half_rn(Wl1[t]); g_w1h[s1 + t] = __float2half_rn(Wr1[t]); }
    if (t < s2) { g_w2h[t] = __float2half_rn(Wl2[t]); g_w2h[s2 + t] = __float2half_rn(Wr2[t]); }
    if (t < s3) g_we1h[t] = __float2half_rn(We1[t]);
    if (t < s4) g_we2h[t] = __float2half_rn(We2[t]);
    if (t < NN * DNODE) g_xh[t] = __float2half_rn(x[t]);
}

// ---------------- graph prep ----------------
__global__ void k_detect(const int* __restrict__ ei) {
    int is64 = 1;
    for (int i = 0; i < 16; i++)
        if (ei[2 * i + 1] != 0) is64 = 0;
    g_is64 = is64;
}
__global__ void k_prep(const int* __restrict__ ei, const int* __restrict__ batch) {
    int t = blockIdx.x * blockDim.x + threadIdx.x;
    int is64 = g_is64;
    if (t < EE) {
        g_src[t] = is64 ? ei[2 * t]        : ei[t];
        g_dst[t] = is64 ? ei[2 * (EE + t)] : ei[EE + t];
    }
    if (t < NN) {
        g_batch[t] = is64 ? batch[2 * t] : batch[t];
        g_deg[t] = 0;
        g_cur[t] = 0;
    }
    if (t < GG) { g_gstart[t] = 0; g_gend[t] = 0; }
    if (t < GG * HC2) g_pool[t] = 0.f;
}
__global__ void k_deg() {
    int e = blockIdx.x * blockDim.x + threadIdx.x;
    if (e < EE) atomicAdd(&g_deg[g_dst[e]], 1);
}
__global__ void k_scan() {
    __shared__ int wsum[8];
    int t = threadIdx.x, lane = t & 31, wid = t >> 5;
    int base = t * 32;
    int loc[32];
    int s = 0;
    #pragma unroll
    for (int i = 0; i < 32; i++) { loc[i] = s; s += g_deg[base + i] + 1; }
    int v = s;
    #pragma unroll
    for (int o = 1; o < 32; o <<= 1) {
        int u = __shfl_up_sync(0xffffffffu, v, o);
        if (lane >= o) v += u;
    }
    if (lane == 31) wsum[wid] = v;
    __syncthreads();
    if (wid == 0) {
        int w = (lane < 8) ? wsum[lane] : 0;
        #pragma unroll
        for (int o = 1; o < 8; o <<= 1) {
            int u = __shfl_up_sync(0xffffffffu, w, o);
            if (lane >= o) w += u;
        }
        if (lane < 8) wsum[lane] = w;
    }
    __syncthreads();
    int p = v - s + (wid > 0 ? wsum[wid - 1] : 0);
    #pragma unroll
    for (int i = 0; i < 32; i++) g_off[base + i] = p + loc[i];
    if (t == 255) g_off[NN] = p + s;
}
__global__ void k_csr() {
    int e = blockIdx.x * blockDim.x + threadIdx.x;
    if (e >= ET) return;
    int s, node;
    if (e < EE) { s = g_src[e]; node = g_dst[e]; } else { s = node = e - EE; }
    int pos = g_off[node] + atomicAdd(&g_cur[node], 1);
    g_pedge[pos] = e;
    g_psrc[pos]  = s;
    g_pdst[pos]  = node;
    if (e < NN) {
        int b = g_batch[e];
        if (e == 0 || g_batch[e - 1] != b) g_gstart[b] = e;
        if (e == NN - 1 || g_batch[e + 1] != b) g_gend[b] = e + 1;
    }
}
__global__ void k_ea2(const float* __restrict__ ea) {
    int t = blockIdx.x * blockDim.x + threadIdx.x;
    if (t >= ET * DEDGE) return;
    int pos = t >> 5, d = t & 31;
    int e = g_pedge[pos];
    float v;
    if (e < EE) {
        v = ea[e * DEDGE + d];
    } else {
        int n = e - EE;
        int s0 = g_off[n], s1 = g_off[n + 1];
        float sum = 0.f;
        for (int p = s0; p < s1; p++) {
            int ee = g_pedge[p];
            if (ee < EE) sum += ea[ee * DEDGE + d];
        }
        v = sum / fmaxf((float)(s1 - s0 - 1), 1.f);
    }
    g_ea2h[t] = __float2half_rn(v);
}

// ---------------- segment softmax + weighted gather (csr order, R13 proven) ----
template <int H, int RELU, int OUTMODE>
__global__ void k_aggregate(const float* __restrict__ bias, void* __restrict__ out) {
    int n = blockIdx.x;
    int h = threadIdx.x >> 5, lane = threadIdx.x & 31;
    int s0 = g_off[n], s1 = g_off[n + 1];
    int cnt = s1 - s0;
    const int HCH = H * (CC / 2);
    const __half2* xl = reinterpret_cast<const __half2*>(g_xl);
    float2 acc[4];
    #pragma unroll
    for (int j = 0; j < 4; j++) acc[j] = make_float2(0.f, 0.f);

    if (cnt <= 64) {
        int cs0 = 0, cs1 = 0;
        float lv0 = -1e30f, lv1 = -1e30f;
        if (lane < cnt) {
            int p = s0 + lane;
            cs0 = g_psrc[p];
            float4 lg = *reinterpret_cast<const float4*>(&g_logits[(p * H + h) * 4]);
            lv0 = (lg.x + lg.y) + (lg.z + lg.w);
        }
        if (lane + 32 < cnt) {
            int p = s0 + lane + 32;
            cs1 = g_psrc[p];
            float4 lg = *reinterpret_cast<const float4*>(&g_logits[(p * H + h) * 4]);
            lv1 = (lg.x + lg.y) + (lg.z + lg.w);
        }
        float mx = warp_max(fmaxf(lv0, lv1));
        float ex0 = (lane < cnt)      ? __expf(lv0 - mx) : 0.f;
        float ex1 = (lane + 32 < cnt) ? __expf(lv1 - mx) : 0.f;
        float inv = 1.f / warp_sum(ex0 + ex1);
        for (int i = 0; i < cnt; i++) {
            int srcl = i & 31;
            float w = __shfl_sync(0xffffffffu, (i < 32) ? ex0 : ex1, srcl) * inv;
            int s = __shfl_sync(0xffffffffu, (i < 32) ? cs0 : cs1, srcl);
            const __half2* row = xl + (size_t)s * HCH + h * 128 + lane;
            #pragma unroll
            for (int j = 0; j < 4; j++) {
                float2 f = __half22float2(row[32 * j]);
                acc[j].x = fmaf(w, f.x, acc[j].x);
                acc[j].y = fmaf(w, f.y, acc[j].y);
            }
        }
    } else {
        float mx = -1e30f;
        for (int i = s0 + lane; i < s1; i += 32) {
            float4 lg = *reinterpret_cast<const float4*>(&g_logits[(i * H + h) * 4]);
            mx = fmaxf(mx, (lg.x + lg.y) + (lg.z + lg.w));
        }
        mx = warp_max(mx);
        float den = 0.f;
        for (int i = s0 + lane; i < s1; i += 32) {
            float4 lg = *reinterpret_cast<const float4*>(&g_logits[(i * H + h) * 4]);
            den += __expf((lg.x + lg.y) + (lg.z + lg.w) - mx);
        }
        den = warp_sum(den);
        float inv = 1.f / den;
        for (int i = s0; i < s1; i++) {
            float4 lg = *reinterpret_cast<const float4*>(&g_logits[(i * H + h) * 4]);
            float w = __expf((lg.x + lg.y) + (lg.z + lg.w) - mx) * inv;
            int s = g_psrc[i];
            const __half2* row = xl + (size_t)s * HCH + h * 128 + lane;
            #pragma unroll
            for (int j = 0; j < 4; j++) {
                float2 f = __half22float2(row[32 * j]);
                acc[j].x = fmaf(w, f.x, acc[j].x);
                acc[j].y = fmaf(w, f.y, acc[j].y);
            }
        }
    }

    int b = (OUTMODE == 2) ? g_batch[n] : 0;
    #pragma unroll
    for (int j = 0; j < 4; j++) {
        int col = h * CC + 2 * (lane + 32 * j);
        float2 bb = *reinterpret_cast<const float2*>(bias + col);
        float v0 = acc[j].x + bb.x, v1 = acc[j].y + bb.y;
        if (RELU) { v0 = fmaxf(v0, 0.f); v1 = fmaxf(v1, 0.f); }
        if (OUTMODE == 1) {
            __half* oh = (__half*)out;
            *reinterpret_cast<__half2*>(oh + (size_t)n * (H * CC) + col) = __floats2half2_rn(v0, v1);
        } else if (OUTMODE == 0) {
            float* of = (float*)out;
            *reinterpret_cast<float2*>(of + (size_t)n * (H * CC) + col) = make_float2(v0, v1);
        } else {
            atomicAdd(&g_pool[b * HC2 + col], v0);
            atomicAdd(&g_pool[b * HC2 + col + 1], v1);
        }
    }
}

// ---------------- fused pool-divide + 3-layer MLP + sigmoid ----------------
__global__ __launch_bounds__(256) void k_mlp(
    const float* __restrict__ W1, const float* __restrict__ b1,
    const float* __restrict__ W2, const float* __restrict__ b2,
    const float* __restrict__ W3, const float* __restrict__ b3,
    float* __restrict__ out)
{
    __shared__ float sp[HC2];
    __shared__ float sm1[512];
    __shared__ float sm2[256];
    int g = blockIdx.x, tid = threadIdx.x;
    int lane = tid & 31, wid = tid >> 5;
    float inv = 1.f / fmaxf((float)(g_gend[g] - g_gstart[g]), 1.f);
    for (int i = tid; i < HC2; i += 256) sp[i] = g_pool[g * HC2 + i] * inv;
    __syncthreads();
    // layer 1: 1024 -> 512, relu
    for (int o = wid; o < 512; o += 8) {
        const float* w = W1 + o * HC2;
        float a = 0.f;
        for (int j = lane; j < HC2; j += 32) a = fmaf(w[j], sp[j], a);
        a = warp_sum(a);
        if (lane == 0) sm1[o] = fmaxf(a + b1[o], 0.f);
    }
    __syncthreads();
    // layer 2: 512 -> 256, relu
    for (int o = wid; o < 256; o += 8) {
        const float* w = W2 + o * 512;
        float a = 0.f;
        for (int j = lane; j < 512; j += 32) a = fmaf(w[j], sm1[j], a);
        a = warp_sum(a);
        if (lane == 0) sm2[o] = fmaxf(a + b2[o], 0.f);
    }
    __syncthreads();
    // layer 3: 256 -> 1, sigmoid
    if (wid == 0) {
        float a = 0.f;
        for (int j = lane; j < 256; j += 32) a = fmaf(W3[j], sm2[j], a);
        a = warp_sum(a);
        if (lane == 0) out[g] = 1.f / (1.f + expf(-(a + b3[0])));
    }
}

// ---------------- host launch ----------------
extern "C" void kernel_launch(void* const* d_in, const int* in_sizes, int n_in,
                              void* d_out, int out_size) {
    const float* x     = (const float*)d_in[0];
    const int*   ei    = (const int*)  d_in[1];
    const float* ea    = (const float*)d_in[2];
    const int*   batch = (const int*)  d_in[3];
    const float* Wl1 = (const float*)d_in[4],  *bl1 = (const float*)d_in[5];
    const float* Wr1 = (const float*)d_in[6],  *br1 = (const float*)d_in[7];
    const float* We1 = (const float*)d_in[8],  *att1 = (const float*)d_in[9];
    const float* bias1 = (const float*)d_in[10];
    const float* Wl2 = (const float*)d_in[11], *bl2 = (const float*)d_in[12];
    const float* Wr2 = (const float*)d_in[13], *br2 = (const float*)d_in[14];
    const float* We2 = (const float*)d_in[15], *att2 = (const float*)d_in[16];
    const float* bias2 = (const float*)d_in[17];
    const float* W1 = (const float*)d_in[18], *b1 = (const float*)d_in[19];
    const float* W2 = (const float*)d_in[20], *b2 = (const float*)d_in[21];
    const float* W3 = (const float*)d_in[22], *b3 = (const float*)d_in[23];
    float* out = (float*)d_out;

    static int s_init = 0;
    static cudaStream_t s1;
    static cudaEvent_t eFork, eJoin;
    if (!s_init) {
        cudaFuncSetAttribute(k_mma_dual, cudaFuncAttributeMaxDynamicSharedMemorySize, GEMM_SMEM_BYTES);
        cudaFuncSetAttribute(k_ee_logits<H1C>, cudaFuncAttributeMaxDynamicSharedMemorySize, EEL_SMEM_BYTES);
        cudaFuncSetAttribute(k_ee_logits<H2C>, cudaFuncAttributeMaxDynamicSharedMemorySize, EEL_SMEM_BYTES);
        cudaStreamCreateWithFlags(&s1, cudaStreamNonBlocking);
        cudaEventCreateWithFlags(&eFork, cudaEventDisableTiming);
        cudaEventCreateWithFlags(&eJoin, cudaEventDisableTiming);
        s_init = 1;
    }

    __half *p_xl, *p_xr, *p_h1h, *p_ea2h, *p_w1h, *p_w2h, *p_we1h, *p_we2h, *p_xh;
    cudaGetSymbolAddress((void**)&p_xl,    g_xl);
    cudaGetSymbolAddress((void**)&p_xr,    g_xr);
    cudaGetSymbolAddress((void**)&p_h1h,   g_h1h);
    cudaGetSymbolAddress((void**)&p_ea2h,  g_ea2h);
    cudaGetSymbolAddress((void**)&p_w1h,   g_w1h);
    cudaGetSymbolAddress((void**)&p_w2h,   g_w2h);
    cudaGetSymbolAddress((void**)&p_we1h,  g_we1h);
    cudaGetSymbolAddress((void**)&p_we2h,  g_we2h);
    cudaGetSymbolAddress((void**)&p_xh,    g_xh);

    // --- fork: graph-prep chain on s1, GEMM path on default stream ---
    cudaEventRecord(eFork, 0);
    cudaStreamWaitEvent(s1, eFork, 0);

    k_detect<<<1, 1, 0, s1>>>(ei);
    k_prep<<<(EE + 255) / 256, 256, 0, s1>>>(ei, batch);
    k_deg<<<(EE + 255) / 256, 256, 0, s1>>>();
    k_scan<<<1, 256, 0, s1>>>();
    k_csr<<<(ET + 255) / 256, 256, 0, s1>>>();
    k_ea2<<<(ET * DEDGE + 255) / 256, 256, 0, s1>>>(ea);
    cudaEventRecord(eJoin, s1);

    k_wconv<<<(HC2 * HC1 + 255) / 256, 256>>>(Wl1, Wr1, Wl2, Wr2, We1, We2, x);
    k_mma_dual<<<dim3(2 * HC1 / 128, NN / 128), 256, GEMM_SMEM_BYTES>>>(
        p_xh, p_w1h, bl1, br1, p_xl, p_xr, NN, 2 * HC1, DNODE);

    cudaStreamWaitEvent(0, eJoin, 0);

    // --- GATv2 layer 1 ---
    k_ee_logits<H1C><<<dim3(HC1 / 128, ET / 128), 256, EEL_SMEM_BYTES>>>(p_ea2h, p_we1h, att1);
    k_aggregate<H1C, 1, 1><<<NN, H1C * 32>>>(bias1, p_h1h);

    // --- GATv2 layer 2 (aggregate pools directly) ---
    k_mma_dual<<<dim3(2 * HC2 / 128, NN / 128), 256, GEMM_SMEM_BYTES>>>(
        p_h1h, p_w2h, bl2, br2, p_xl, p_xr, NN, 2 * HC2, HC1);
    k_ee_logits<H2C><<<dim3(HC2 / 128, ET / 128), 256, EEL_SMEM_BYTES>>>(p_ea2h, p_we2h, att2);
    k_aggregate<H2C, 0, 2><<<NN, H2C * 32>>>(bias2, nullptr);

    // --- fused pool-divide + MLP + sigmoid ---
    k_mlp<<<GG, 256>>>(W1, b1, W2, b2, W3, b3, out);
}

// round 16
// speedup vs baseline: 1.8819x; 1.0027x over previous
#include <cuda_runtime.h>
#include <cuda_fp16.h>
#include <math.h>
#include <stdint.h>

// ---------------- problem constants ----------------
#define NN   8192
#define EE   65536
#define GG   64
#define DNODE 64
#define DEDGE 32
#define CC   256
#define H1C  8
#define H2C  4
#define ET   (EE + NN)          // 73728 = 576*128
#define HC1  (H1C * CC)         // 2048
#define HC2  (H2C * CC)         // 1024
#define NEG_SLOPE 0.2f

// ---------------- device scratch ----------------
__device__ int    g_src[EE];
__device__ int    g_dst[EE];
__device__ int    g_batch[NN];
__device__ int    g_deg[NN];
__device__ int    g_cur[NN];
__device__ int    g_off[NN + 1];
__device__ int    g_gstart[GG];
__device__ int    g_gend[GG];
__device__ int    g_pedge[ET];
__device__ int    g_psrc[ET];
__device__ int    g_pdst[ET];
__device__ __half g_ea2h[ET * DEDGE];
__device__ __half g_xh[NN * DNODE];
__device__ __half g_xl[NN * HC1];
__device__ __half g_xr[NN * HC1];
__device__ __half g_h1h[NN * HC1];
__device__ float  g_logits[ET * H1C * 4];
__device__ float  g_pool[GG * HC2];
__device__ __half g_w1h[2 * HC1 * DNODE];
__device__ __half g_w2h[2 * HC2 * HC1];
__device__ __half g_we1h[HC1 * DEDGE];
__device__ __half g_we2h[HC2 * DEDGE];

// ---------------- helpers ----------------
__device__ __forceinline__ float warp_sum(float v) {
    #pragma unroll
    for (int o = 16; o; o >>= 1) v += __shfl_xor_sync(0xffffffffu, v, o);
    return v;
}
__device__ __forceinline__ float warp_max(float v) {
    #pragma unroll
    for (int o = 16; o; o >>= 1) v = fmaxf(v, __shfl_xor_sync(0xffffffffu, v, o));
    return v;
}
__device__ __forceinline__ uint32_t smem_u32(const void* p) {
    uint32_t a;
    asm("{ .reg .u64 t; cvta.to.shared.u64 t, %1; cvt.u32.u64 %0, t; }" : "=r"(a) : "l"(p));
    return a;
}
__device__ __forceinline__ void mma_f16(float* c, uint4 a, uint2 b) {
    asm volatile(
        "mma.sync.aligned.m16n8k16.row.col.f32.f16.f16.f32 "
        "{%0,%1,%2,%3},{%4,%5,%6,%7},{%8,%9},{%0,%1,%2,%3};"
        : "+f"(c[0]), "+f"(c[1]), "+f"(c[2]), "+f"(c[3])
        : "r"(a.x), "r"(a.y), "r"(a.z), "r"(a.w), "r"(b.x), "r"(b.y));
}
__device__ __forceinline__ uint4 ldsm4(uint32_t addr) {
    uint4 r;
    asm volatile("ldmatrix.sync.aligned.m8n8.x4.shared.b16 {%0,%1,%2,%3}, [%4];"
        : "=r"(r.x), "=r"(r.y), "=r"(r.z), "=r"(r.w) : "r"(addr));
    return r;
}
__device__ __forceinline__ void cp16(uint32_t dst, const void* src) {
    asm volatile("cp.async.cg.shared.global [%0], [%1], 16;" :: "r"(dst), "l"(src));
}

// =================================================================
// cp.async + ldmatrix fp16 GEMM (3-stage, XOR swizzle) — proven R7-15.
// =================================================================
#define GEMM_STAGE_BYTES 32768
#define GEMM_SMEM_BYTES  (3 * GEMM_STAGE_BYTES)

__device__ __forceinline__ void issue_stage(
    const __half* __restrict__ A, const __half* __restrict__ B, int K,
    int rowBase, int colBase, int k0, uint32_t abase, int tid)
{
    #pragma unroll
    for (int i = 0; i < 4; i++) {
        int id = i * 256 + tid;
        int r = id >> 3, c = id & 7;
        uint32_t off = (uint32_t)(r * 128 + ((c ^ (r & 7)) << 4));
        cp16(abase + off,         A + (size_t)(rowBase + r) * K + k0 + c * 8);
        cp16(abase + 16384 + off, B + (size_t)(colBase + r) * K + k0 + c * 8);
    }
    asm volatile("cp.async.commit_group;" ::: "memory");
}

__global__ __launch_bounds__(256, 2) void k_mma_dual(
    const __half* __restrict__ A, const __half* __restrict__ B,
    const float* __restrict__ biasL, const float* __restrict__ biasR,
    __half* __restrict__ outL, __half* __restrict__ outR,
    int N, int K)
{
    extern __shared__ char smem[];
    uint32_t sb = smem_u32(smem);
    int tid = threadIdx.x;
    int wid = tid >> 5, lane = tid & 31;
    int mw = wid & 3, nw = wid >> 2;
    int gid = lane >> 2, tig = lane & 3;
    int rowBase = blockIdx.y * 128, colBase = blockIdx.x * 128;

    float acc[2][8][4];
    #pragma unroll
    for (int mt = 0; mt < 2; mt++)
        #pragma unroll
        for (int nt = 0; nt < 8; nt++)
            #pragma unroll
            for (int q = 0; q < 4; q++) acc[mt][nt][q] = 0.f;

    const int NCH = K >> 6;
    issue_stage(A, B, K, rowBase, colBase, 0, sb, tid);
    if (NCH > 1) issue_stage(A, B, K, rowBase, colBase, 64, sb + GEMM_STAGE_BYTES, tid);

    int arow = mw * 32 + (lane & 15);
    int achoff = lane >> 4;
    int brow = nw * 64 + ((lane >> 4) << 3) + (lane & 7);
    int bchoff = (lane >> 3) & 1;

    for (int c = 0; c < NCH; c++) {
        if (c + 2 <= NCH) asm volatile("cp.async.wait_group 1;" ::: "memory");
        else              asm volatile("cp.async.wait_group 0;" ::: "memory");
        __syncthreads();
        if (c + 2 < NCH)
            issue_stage(A, B, K, rowBase, colBase, (c + 2) << 6,
                        sb + ((c + 2) % 3) * GEMM_STAGE_BYTES, tid);

        uint32_t Ab = sb + (c % 3) * GEMM_STAGE_BYTES;
        uint32_t Bb = Ab + 16384;
        #pragma unroll
        for (int kstep = 0; kstep < 4; kstep++) {
            uint4 afr[2];
            #pragma unroll
            for (int mt = 0; mt < 2; mt++) {
                int row = arow + mt * 16;
                int ch = kstep * 2 + achoff;
                afr[mt] = ldsm4(Ab + row * 128 + ((ch ^ (row & 7)) << 4));
            }
            uint2 bfr[8];
            #pragma unroll
            for (int ntp = 0; ntp < 4; ntp++) {
                int row = brow + ntp * 16;
                int ch = kstep * 2 + bchoff;
                uint4 t = ldsm4(Bb + row * 128 + ((ch ^ (row & 7)) << 4));
                bfr[2 * ntp]     = make_uint2(t.x, t.y);
                bfr[2 * ntp + 1] = make_uint2(t.z, t.w);
            }
            #pragma unroll
            for (int mt = 0; mt < 2; mt++)
                #pragma unroll
                for (int nt = 0; nt < 8; nt++)
                    mma_f16(acc[mt][nt], afr[mt], bfr[nt]);
        }
    }

    int halfN = N >> 1;
    bool isR = (colBase >= halfN);
    const float* bias = isR ? biasR : biasL;
    __half* outp = isR ? outR : outL;
    int cb = colBase - (isR ? halfN : 0);

    #pragma unroll
    for (int mt = 0; mt < 2; mt++) {
        int row0 = rowBase + mw * 32 + mt * 16 + gid;
        #pragma unroll
        for (int nt = 0; nt < 8; nt++) {
            int col = cb + nw * 64 + nt * 8 + tig * 2;
            float b0 = bias[col], b1 = bias[col + 1];
            float c0 = acc[mt][nt][0] + b0, c1 = acc[mt][nt][1] + b1;
            float c2 = acc[mt][nt][2] + b0, c3 = acc[mt][nt][3] + b1;
            *reinterpret_cast<__half2*>(outp + (size_t)row0 * halfN + col)       = __floats2half2_rn(c0, c1);
            *reinterpret_cast<__half2*>(outp + (size_t)(row0 + 8) * halfN + col) = __floats2half2_rn(c2, c3);
        }
    }
}

// =================================================================
// Fused edge-feature GEMM + logits, smem-staged xl/xr gathers (R11).
// =================================================================
#define EEL_XL_OFF 16384
#define EEL_XR_OFF (16384 + 128 * 272)
#define EEL_SMEM_BYTES (16384 + 2 * 128 * 272)

__device__ __forceinline__ void ldg_tile_h(
    const __half* __restrict__ A, const __half* __restrict__ B, int K,
    int rowBase, int colBase, int kc, int tid, uint2* pa, uint2* pb)
{
    #pragma unroll
    for (int i = 0; i < 4; i++) {
        int id = i * 256 + tid;
        int r = id >> 3, c4 = id & 7;
        pa[i] = *reinterpret_cast<const uint2*>(A + (size_t)(rowBase + r) * K + kc + c4 * 4);
        pb[i] = *reinterpret_cast<const uint2*>(B + (size_t)(colBase + r) * K + kc + c4 * 4);
    }
}
__device__ __forceinline__ void sts_tile(
    uint32_t* __restrict__ sA, uint32_t* __restrict__ sB,
    int tid, const uint2* pa, const uint2* pb)
{
    #pragma unroll
    for (int i = 0; i < 4; i++) {
        int id = i * 256 + tid;
        int r = id >> 3, c4 = id & 7;
        int kstep = c4 >> 2;
        int pl = (c4 & 3) * 2;
        int mtile = r >> 4, ri = r & 15;
        int regA = ((pl & 4) ? 2 : 0) + (ri >> 3);
        int laneA = (ri & 7) * 4 + (pl & 3);
        int baseA = (kstep * 8 + mtile) * 128;
        sA[baseA + laneA * 4 + regA]       = pa[i].x;
        sA[baseA + (laneA + 1) * 4 + regA] = pa[i].y;
        int ntile = r >> 3, ni = r & 7;
        int regB = (pl & 4) ? 1 : 0;
        int laneB = ni * 4 + (pl & 3);
        int baseB = (kstep * 16 + ntile) * 64;
        sB[baseB + laneB * 2 + regB]       = pb[i].x;
        sB[baseB + (laneB + 1) * 2 + regB] = pb[i].y;
    }
}

template <int H>
__global__ __launch_bounds__(256) void k_ee_logits(
    const __half* __restrict__ A, const __half* __restrict__ B,
    const float* __restrict__ att)
{
    extern __shared__ uint32_t sm[];
    uint32_t sb = smem_u32(sm);
    int tid = threadIdx.x;
    int wid = tid >> 5, lane = tid & 31;
    int mw = wid & 3, nw = wid >> 2;
    int gid = lane >> 2, tig = lane & 3;
    int rowBase = blockIdx.y * 128, colBase = blockIdx.x * 128;
    const int HC = H * CC;

    #pragma unroll
    for (int i = 0; i < 8; i++) {
        int idx = i * 256 + tid;
        int el = idx >> 4, p = idx & 15;
        int eg = rowBase + el;
        int s = g_psrc[eg], d = g_pdst[eg];
        cp16(sb + EEL_XL_OFF + el * 272 + p * 16, g_xl + (size_t)s * HC + colBase + p * 8);
        cp16(sb + EEL_XR_OFF + el * 272 + p * 16, g_xr + (size_t)d * HC + colBase + p * 8);
    }
    asm volatile("cp.async.commit_group;" ::: "memory");

    float acc[2][8][4];
    #pragma unroll
    for (int mt = 0; mt < 2; mt++)
        #pragma unroll
        for (int nt = 0; nt < 8; nt++)
            #pragma unroll
            for (int q = 0; q < 4; q++) acc[mt][nt][q] = 0.f;

    uint2 pa[4], pb[4];
    ldg_tile_h(A, B, DEDGE, rowBase, colBase, 0, tid, pa, pb);
    sts_tile(sm, sm + 2048, tid, pa, pb);
    __syncthreads();

    #pragma unroll
    for (int kstep = 0; kstep < 2; kstep++) {
        uint4 afr[2];
        #pragma unroll
        for (int mt = 0; mt < 2; mt++)
            afr[mt] = *reinterpret_cast<const uint4*>(
                sm + (kstep * 8 + mw * 2 + mt) * 128 + lane * 4);
        uint2 bfr[8];
        #pragma unroll
        for (int nt = 0; nt < 8; nt++)
            bfr[nt] = *reinterpret_cast<const uint2*>(
                sm + 2048 + (kstep * 16 + nw * 8 + nt) * 64 + lane * 2);
        #pragma unroll
        for (int mt = 0; mt < 2; mt++)
            #pragma unroll
            for (int nt = 0; nt < 8; nt++)
                mma_f16(acc[mt][nt], afr[mt], bfr[nt]);
    }

    asm volatile("cp.async.wait_group 0;" ::: "memory");
    __syncthreads();

    int h = colBase >> 8;
    int q = ((blockIdx.x & 1) << 1) | nw;
    const __half2* sXL = reinterpret_cast<const __half2*>((const char*)sm + EEL_XL_OFF);
    const __half2* sXR = reinterpret_cast<const __half2*>((const char*)sm + EEL_XR_OFF);

    #pragma unroll
    for (int mt = 0; mt < 2; mt++) {
        int el0 = mw * 32 + mt * 16 + gid;
        int el1 = el0 + 8;
        float p0 = 0.f, p1 = 0.f;
        #pragma unroll
        for (int nt = 0; nt < 8; nt++) {
            int coff = nw * 32 + nt * 4 + tig;
            int col = colBase + nw * 64 + nt * 8 + tig * 2;
            float2 at = *reinterpret_cast<const float2*>(att + h * CC + (col & (CC - 1)));
            float2 a0 = __half22float2(sXL[el0 * 68 + coff]);
            float2 b0 = __half22float2(sXR[el0 * 68 + coff]);
            float2 a1 = __half22float2(sXL[el1 * 68 + coff]);
            float2 b1 = __half22float2(sXR[el1 * 68 + coff]);
            float v0 = acc[mt][nt][0] + a0.x + b0.x;
            float v1 = acc[mt][nt][1] + a0.y + b0.y;
            float v2 = acc[mt][nt][2] + a1.x + b1.x;
            float v3 = acc[mt][nt][3] + a1.y + b1.y;
            v0 = (v0 > 0.f) ? v0 : NEG_SLOPE * v0;
            v1 = (v1 > 0.f) ? v1 : NEG_SLOPE * v1;
            v2 = (v2 > 0.f) ? v2 : NEG_SLOPE * v2;
            v3 = (v3 > 0.f) ? v3 : NEG_SLOPE * v3;
            p0 += v0 * at.x + v1 * at.y;
            p1 += v2 * at.x + v3 * at.y;
        }
        p0 += __shfl_xor_sync(0xffffffffu, p0, 1);
        p0 += __shfl_xor_sync(0xffffffffu, p0, 2);
        p1 += __shfl_xor_sync(0xffffffffu, p1, 1);
        p1 += __shfl_xor_sync(0xffffffffu, p1, 2);
        if (tig == 0) {
            g_logits[((rowBase + el0) * H + h) * 4 + q] = p0;
            g_logits[((rowBase + el1) * H + h) * 4 + q] = p1;
        }
    }
}

// ---------------- weight / input conversion (split) ----------------
__global__ void k_wconv1(const float* __restrict__ Wl1, const float* __restrict__ Wr1,
                         const float* __restrict__ x)
{
    int t = blockIdx.x * blockDim.x + threadIdx.x;
    const int s1 = HC1 * DNODE;
    if (t < s1) { g_w1h[t] = __float2half_rn(Wl1[t]); g_w1h[s1 + t] = __float2half_rn(Wr1[t]); }
    if (t < NN * DNODE) g_xh[t] = __float2half_rn(x[t]);
}
__global__ void k_wconv2(const float* __restrict__ Wl2, const float* __restrict__ Wr2,
                         const float* __restrict__ We1, const float* __restrict__ We2)
{
    int t = blockIdx.x * blockDim.x + threadIdx.x;
    const int s2 = HC2 * HC1;
    const int s3 = HC1 * DEDGE;
    const int s4 = HC2 * DEDGE;
    if (t < s2) { g_w2h[t] = __float2half_rn(Wl2[t]); g_w2h[s2 + t] = __float2half_rn(Wr2[t]); }
    if (t < s3) g_we1h[t] = __float2half_rn(We1[t]);
    if (t < s4) g_we2h[t] = __float2half_rn(We2[t]);
}

// ---------------- graph prep (detect merged in) ----------------
__global__ void k_prep(const int* __restrict__ ei, const int* __restrict__ batch) {
    int is64 = 1;
    #pragma unroll
    for (int i = 0; i < 16; i++)
        if (ei[2 * i + 1] != 0) is64 = 0;
    int t = blockIdx.x * blockDim.x + threadIdx.x;
    if (t < EE) {
        g_src[t] = is64 ? ei[2 * t]        : ei[t];
        g_dst[t] = is64 ? ei[2 * (EE + t)] : ei[EE + t];
    }
    if (t < NN) {
        g_batch[t] = is64 ? batch[2 * t] : batch[t];
        g_deg[t] = 0;
        g_cur[t] = 0;
    }
    if (t < GG) { g_gstart[t] = 0; g_gend[t] = 0; }
    if (t < GG * HC2) g_pool[t] = 0.f;
}
__global__ void k_deg() {
    int e = blockIdx.x * blockDim.x + threadIdx.x;
    if (e < EE) atomicAdd(&g_deg[g_dst[e]], 1);
}
__global__ void k_scan() {
    __shared__ int wsum[8];
    int t = threadIdx.x, lane = t & 31, wid = t >> 5;
    int base = t * 32;
    int loc[32];
    int s = 0;
    #pragma unroll
    for (int i = 0; i < 32; i++) { loc[i] = s; s += g_deg[base + i] + 1; }
    int v = s;
    #pragma unroll
    for (int o = 1; o < 32; o <<= 1) {
        int u = __shfl_up_sync(0xffffffffu, v, o);
        if (lane >= o) v += u;
    }
    if (lane == 31) wsum[wid] = v;
    __syncthreads();
    if (wid == 0) {
        int w = (lane < 8) ? wsum[lane] : 0;
        #pragma unroll
        for (int o = 1; o < 8; o <<= 1) {
            int u = __shfl_up_sync(0xffffffffu, w, o);
            if (lane >= o) w += u;
        }
        if (lane < 8) wsum[lane] = w;
    }
    __syncthreads();
    int p = v - s + (wid > 0 ? wsum[wid - 1] : 0);
    #pragma unroll
    for (int i = 0; i < 32; i++) g_off[base + i] = p + loc[i];
    if (t == 255) g_off[NN] = p + s;
}
__global__ void k_csr() {
    int e = blockIdx.x * blockDim.x + threadIdx.x;
    if (e >= ET) return;
    int s, node;
    if (e < EE) { s = g_src[e]; node = g_dst[e]; } else { s = node = e - EE; }
    int pos = g_off[node] + atomicAdd(&g_cur[node], 1);
    g_pedge[pos] = e;
    g_psrc[pos]  = s;
    g_pdst[pos]  = node;
    if (e < NN) {
        int b = g_batch[e];
        if (e == 0 || g_batch[e - 1] != b) g_gstart[b] = e;
        if (e == NN - 1 || g_batch[e + 1] != b) g_gend[b] = e + 1;
    }
}
__global__ void k_ea2(const float* __restrict__ ea) {
    int t = blockIdx.x * blockDim.x + threadIdx.x;
    if (t >= ET * DEDGE) return;
    int pos = t >> 5, d = t & 31;
    int e = g_pedge[pos];
    float v;
    if (e < EE) {
        v = ea[e * DEDGE + d];
    } else {
        int n = e - EE;
        int s0 = g_off[n], s1 = g_off[n + 1];
        float sum = 0.f;
        for (int p = s0; p < s1; p++) {
            int ee = g_pedge[p];
            if (ee < EE) sum += ea[ee * DEDGE + d];
        }
        v = sum / fmaxf((float)(s1 - s0 - 1), 1.f);
    }
    g_ea2h[t] = __float2half_rn(v);
}

// ---------------- segment softmax + weighted gather (csr order, R13 proven) ----
template <int H, int RELU, int OUTMODE>
__global__ void k_aggregate(const float* __restrict__ bias, void* __restrict__ out, int nbase) {
    int n = blockIdx.x + nbase;
    int h = threadIdx.x >> 5, lane = threadIdx.x & 31;
    int s0 = g_off[n], s1 = g_off[n + 1];
    int cnt = s1 - s0;
    const int HCH = H * (CC / 2);
    const __half2* xl = reinterpret_cast<const __half2*>(g_xl);
    float2 acc[4];
    #pragma unroll
    for (int j = 0; j < 4; j++) acc[j] = make_float2(0.f, 0.f);

    if (cnt <= 64) {
        int cs0 = 0, cs1 = 0;
        float lv0 = -1e30f, lv1 = -1e30f;
        if (lane < cnt) {
            int p = s0 + lane;
            cs0 = g_psrc[p];
            float4 lg = *reinterpret_cast<const float4*>(&g_logits[(p * H + h) * 4]);
            lv0 = (lg.x + lg.y) + (lg.z + lg.w);
        }
        if (lane + 32 < cnt) {
            int p = s0 + lane + 32;
            cs1 = g_psrc[p];
            float4 lg = *reinterpret_cast<const float4*>(&g_logits[(p * H + h) * 4]);
            lv1 = (lg.x + lg.y) + (lg.z + lg.w);
        }
        float mx = warp_max(fmaxf(lv0, lv1));
        float ex0 = (lane < cnt)      ? __expf(lv0 - mx) : 0.f;
        float ex1 = (lane + 32 < cnt) ? __expf(lv1 - mx) : 0.f;
        float inv = 1.f / warp_sum(ex0 + ex1);
        for (int i = 0; i < cnt; i++) {
            int srcl = i & 31;
            float w = __shfl_sync(0xffffffffu, (i < 32) ? ex0 : ex1, srcl) * inv;
            int s = __shfl_sync(0xffffffffu, (i < 32) ? cs0 : cs1, srcl);
            const __half2* row = xl + (size_t)s * HCH + h * 128 + lane;
            #pragma unroll
            for (int j = 0; j < 4; j++) {
                float2 f = __half22float2(row[32 * j]);
                acc[j].x = fmaf(w, f.x, acc[j].x);
                acc[j].y = fmaf(w, f.y, acc[j].y);
            }
        }
    } else {
        float mx = -1e30f;
        for (int i = s0 + lane; i < s1; i += 32) {
            float4 lg = *reinterpret_cast<const float4*>(&g_logits[(i * H + h) * 4]);
            mx = fmaxf(mx, (lg.x + lg.y) + (lg.z + lg.w));
        }
        mx = warp_max(mx);
        float den = 0.f;
        for (int i = s0 + lane; i < s1; i += 32) {
            float4 lg = *reinterpret_cast<const float4*>(&g_logits[(i * H + h) * 4]);
            den += __expf((lg.x + lg.y) + (lg.z + lg.w) - mx);
        }
        den = warp_sum(den);
        float inv = 1.f / den;
        for (int i = s0; i < s1; i++) {
            float4 lg = *reinterpret_cast<const float4*>(&g_logits[(i * H + h) * 4]);
            float w = __expf((lg.x + lg.y) + (lg.z + lg.w) - mx) * inv;
            int s = g_psrc[i];
            const __half2* row = xl + (size_t)s * HCH + h * 128 + lane;
            #pragma unroll
            for (int j = 0; j < 4; j++) {
                float2 f = __half22float2(row[32 * j]);
                acc[j].x = fmaf(w, f.x, acc[j].x);
                acc[j].y = fmaf(w, f.y, acc[j].y);
            }
        }
    }

    int b = (OUTMODE == 2) ? g_batch[n] : 0;
    #pragma unroll
    for (int j = 0; j < 4; j++) {
        int col = h * CC + 2 * (lane + 32 * j);
        float2 bb = *reinterpret_cast<const float2*>(bias + col);
        float v0 = acc[j].x + bb.x, v1 = acc[j].y + bb.y;
        if (RELU) { v0 = fmaxf(v0, 0.f); v1 = fmaxf(v1, 0.f); }
        if (OUTMODE == 1) {
            __half* oh = (__half*)out;
            *reinterpret_cast<__half2*>(oh + (size_t)n * (H * CC) + col) = __floats2half2_rn(v0, v1);
        } else {
            atomicAdd(&g_pool[b * HC2 + col], v0);
            atomicAdd(&g_pool[b * HC2 + col + 1], v1);
        }
    }
}

// ---------------- fused pool-divide + 3-layer MLP + sigmoid ----------------
__global__ __launch_bounds__(256) void k_mlp(
    const float* __restrict__ W1, const float* __restrict__ b1,
    const float* __restrict__ W2, const float* __restrict__ b2,
    const float* __restrict__ W3, const float* __restrict__ b3,
    float* __restrict__ out)
{
    __shared__ float sp[HC2];
    __shared__ float sm1[512];
    __shared__ float sm2[256];
    int g = blockIdx.x, tid = threadIdx.x;
    int lane = tid & 31, wid = tid >> 5;
    float inv = 1.f / fmaxf((float)(g_gend[g] - g_gstart[g]), 1.f);
    for (int i = tid; i < HC2; i += 256) sp[i] = g_pool[g * HC2 + i] * inv;
    __syncthreads();
    for (int o = wid; o < 512; o += 8) {
        const float* w = W1 + o * HC2;
        float a = 0.f;
        for (int j = lane; j < HC2; j += 32) a = fmaf(w[j], sp[j], a);
        a = warp_sum(a);
        if (lane == 0) sm1[o] = fmaxf(a + b1[o], 0.f);
    }
    __syncthreads();
    for (int o = wid; o < 256; o += 8) {
        const float* w = W2 + o * 512;
        float a = 0.f;
        for (int j = lane; j < 512; j += 32) a = fmaf(w[j], sm1[j], a);
        a = warp_sum(a);
        if (lane == 0) sm2[o] = fmaxf(a + b2[o], 0.f);
    }
    __syncthreads();
    if (wid == 0) {
        float a = 0.f;
        for (int j = lane; j < 256; j += 32) a = fmaf(W3[j], sm2[j], a);
        a = warp_sum(a);
        if (lane == 0) out[g] = 1.f / (1.f + expf(-(a + b3[0])));
    }
}

// ---------------- host launch ----------------
extern "C" void kernel_launch(void* const* d_in, const int* in_sizes, int n_in,
                              void* d_out, int out_size) {
    const float* x     = (const float*)d_in[0];
    const int*   ei    = (const int*)  d_in[1];
    const float* ea    = (const float*)d_in[2];
    const int*   batch = (const int*)  d_in[3];
    const float* Wl1 = (const float*)d_in[4],  *bl1 = (const float*)d_in[5];
    const float* Wr1 = (const float*)d_in[6],  *br1 = (const float*)d_in[7];
    const float* We1 = (const float*)d_in[8],  *att1 = (const float*)d_in[9];
    const float* bias1 = (const float*)d_in[10];
    const float* Wl2 = (const float*)d_in[11], *bl2 = (const float*)d_in[12];
    const float* Wr2 = (const float*)d_in[13], *br2 = (const float*)d_in[14];
    const float* We2 = (const float*)d_in[15], *att2 = (const float*)d_in[16];
    const float* bias2 = (const float*)d_in[17];
    const float* W1 = (const float*)d_in[18], *b1 = (const float*)d_in[19];
    const float* W2 = (const float*)d_in[20], *b2 = (const float*)d_in[21];
    const float* W3 = (const float*)d_in[22], *b3 = (const float*)d_in[23];
    float* out = (float*)d_out;

    static int s_init = 0;
    static cudaStream_t s1, s2;
    static cudaEvent_t eFork, eJoin, eA, eM;
    if (!s_init) {
        cudaFuncSetAttribute(k_mma_dual, cudaFuncAttributeMaxDynamicSharedMemorySize, GEMM_SMEM_BYTES);
        cudaFuncSetAttribute(k_ee_logits<H1C>, cudaFuncAttributeMaxDynamicSharedMemorySize, EEL_SMEM_BYTES);
        cudaFuncSetAttribute(k_ee_logits<H2C>, cudaFuncAttributeMaxDynamicSharedMemorySize, EEL_SMEM_BYTES);
        cudaStreamCreateWithFlags(&s1, cudaStreamNonBlocking);
        cudaStreamCreateWithFlags(&s2, cudaStreamNonBlocking);
        cudaEventCreateWithFlags(&eFork, cudaEventDisableTiming);
        cudaEventCreateWithFlags(&eJoin, cudaEventDisableTiming);
        cudaEventCreateWithFlags(&eA, cudaEventDisableTiming);
        cudaEventCreateWithFlags(&eM, cudaEventDisableTiming);
        s_init = 1;
    }

    __half *p_xl, *p_xr, *p_h1h, *p_ea2h, *p_w1h, *p_w2h, *p_we1h, *p_we2h, *p_xh;
    cudaGetSymbolAddress((void**)&p_xl,    g_xl);
    cudaGetSymbolAddress((void**)&p_xr,    g_xr);
    cudaGetSymbolAddress((void**)&p_h1h,   g_h1h);
    cudaGetSymbolAddress((void**)&p_ea2h,  g_ea2h);
    cudaGetSymbolAddress((void**)&p_w1h,   g_w1h);
    cudaGetSymbolAddress((void**)&p_w2h,   g_w2h);
    cudaGetSymbolAddress((void**)&p_we1h,  g_we1h);
    cudaGetSymbolAddress((void**)&p_we2h,  g_we2h);
    cudaGetSymbolAddress((void**)&p_xh,    g_xh);

    // --- fork: graph-prep + big weight conversion on s1 ---
    cudaEventRecord(eFork, 0);
    cudaStreamWaitEvent(s1, eFork, 0);

    k_prep<<<(EE + 255) / 256, 256, 0, s1>>>(ei, batch);
    k_wconv2<<<(HC2 * HC1 + 255) / 256, 256, 0, s1>>>(Wl2, Wr2, We1, We2);
    k_deg<<<(EE + 255) / 256, 256, 0, s1>>>();
    k_scan<<<1, 256, 0, s1>>>();
    k_csr<<<(ET + 255) / 256, 256, 0, s1>>>();
    k_ea2<<<(ET * DEDGE + 255) / 256, 256, 0, s1>>>(ea);
    cudaEventRecord(eJoin, s1);

    // default: light conversion + layer-1 GEMM
    k_wconv1<<<(NN * DNODE + 255) / 256, 256>>>(Wl1, Wr1, x);
    k_mma_dual<<<dim3(2 * HC1 / 128, NN / 128), 256, GEMM_SMEM_BYTES>>>(
        p_xh, p_w1h, bl1, br1, p_xl, p_xr, 2 * HC1, DNODE);

    cudaStreamWaitEvent(0, eJoin, 0);

    // --- GATv2 layer 1 ---
    k_ee_logits<H1C><<<dim3(HC1 / 128, ET / 128), 256, EEL_SMEM_BYTES>>>(p_ea2h, p_we1h, att1);
    k_aggregate<H1C, 1, 1><<<NN / 2, H1C * 32>>>(bias1, p_h1h, 0);
    cudaEventRecord(eA, 0);
    k_aggregate<H1C, 1, 1><<<NN / 2, H1C * 32>>>(bias1, p_h1h, NN / 2);

    // --- layer-2 GEMM pipelined with agg1 second half ---
    // s2: first half rows (needs only agg1a)
    cudaStreamWaitEvent(s2, eA, 0);
    k_mma_dual<<<dim3(2 * HC2 / 128, NN / 256), 256, GEMM_SMEM_BYTES, s2>>>(
        p_h1h, p_w2h, bl2, br2, p_xl, p_xr, 2 * HC2, HC1);
    cudaEventRecord(eM, s2);
    // default: second half rows (after agg1b, in-order)
    k_mma_dual<<<dim3(2 * HC2 / 128, NN / 256), 256, GEMM_SMEM_BYTES>>>(
        p_h1h + (size_t)(NN / 2) * HC1, p_w2h, bl2, br2,
        p_xl + (size_t)(NN / 2) * HC2, p_xr + (size_t)(NN / 2) * HC2, 2 * HC2, HC1);
    cudaStreamWaitEvent(0, eM, 0);

    // --- GATv2 layer 2 (aggregate pools directly) ---
    k_ee_logits<H2C><<<dim3(HC2 / 128, ET / 128), 256, EEL_SMEM_BYTES>>>(p_ea2h, p_we2h, att2);
    k_aggregate<H2C, 0, 2><<<NN, H2C * 32>>>(bias2, nullptr, 0);

    // --- fused pool-divide + MLP + sigmoid ---
    k_mlp<<<GG, 256>>>(W1, b1, W2, b2, W3, b3, out);
}